// round 1
// baseline (speedup 1.0000x reference)
#include <cuda_runtime.h>
#include <cuda_bf16.h>
#include <cstdint>

// Problem constants
#define Bb    4
#define Nn    32768
#define Kk    16
#define CIN   64
#define COUT  128
#define CD    32
#define CALL  96
#define NP    (Bb * Nn)          // 131072 points

// -------------------- scratch (allocation-free: device globals) ------------
__device__ float d_prel[(size_t)NP * 48];           // (NP, 3K)   25 MB
__device__ float d_h[(size_t)NP * 256];             // (NP, K*K)  134 MB
__device__ float d_X[(size_t)NP * 256];             // (NP, K*K)  134 MB
__device__ float d_fall[(size_t)NP * 1536];         // (NP, K*C_ALL) 805 MB (transformed in place)

// ============================================================================
// K1: gather neighbors, compute p_rel, f_delta, stage f_all (pre-transform)
//     warp per point, 8 warps / CTA
// ============================================================================
__global__ void __launch_bounds__(256) gather_kernel(
    const float* __restrict__ coords, const float* __restrict__ feats,
    const int* __restrict__ knn, const float* __restrict__ Wd,
    const float* __restrict__ bd)
{
    __shared__ float sWd[96];
    __shared__ float sbd[32];
    __shared__ int   snb[8][16];

    int tid = threadIdx.x;
    if (tid < 96) sWd[tid] = Wd[tid];
    if (tid < 32) sbd[tid] = bd[tid];
    __syncthreads();

    int wid = tid >> 5, lane = tid & 31;
    size_t p = (size_t)blockIdx.x * 8 + wid;
    int b = (int)(p >> 15);                       // p / N

    float cx = coords[p * 3 + 0];
    float cy = coords[p * 3 + 1];
    float cz = coords[p * 3 + 2];

    if (lane < 16) {
        int nb = knn[p * 16 + lane];
        snb[wid][lane] = nb;
        size_t q = ((size_t)b * Nn + nb) * 3;
        float prx = coords[q + 0] - cx;
        float pry = coords[q + 1] - cy;
        float prz = coords[q + 2] - cz;
        float* pf = d_prel + p * 48 + lane * 3;
        pf[0] = prx; pf[1] = pry; pf[2] = prz;
        // f_delta = relu(p_rel @ Wd + bd) -> f_all[:, 0:32]
        float* gout = d_fall + p * 1536 + (size_t)lane * 96;
#pragma unroll
        for (int c = 0; c < 32; c++) {
            float v = sbd[c] + prx * sWd[c] + pry * sWd[32 + c] + prz * sWd[64 + c];
            gout[c] = fmaxf(v, 0.0f);
        }
    }
    __syncwarp();

    // gather neighbor features -> f_all[:, 32:96]  (coalesced over lanes)
    size_t fb = (size_t)b * Nn * CIN;
    float* gbase = d_fall + p * 1536;
#pragma unroll
    for (int j = 0; j < 16; j++) {
        int nb = snb[wid][j];
        const float* fr = feats + fb + (size_t)nb * CIN;
        gbase[j * 96 + 32 + lane] = fr[lane];
        gbase[j * 96 + 64 + lane] = fr[32 + lane];
    }
}

// ============================================================================
// Generic tiled SGEMM: C(MxN) = op(A(MxK) @ B(KxN) + bias), row-major.
// BM=128, BN=128, BK=8, TM=TN=8, 256 threads. Requires M%128==0, N%128==0, K%8==0.
// ============================================================================
#define GBM 128
#define GBN 128
#define GBK 8
#define GTM 8
#define GTN 8

__global__ void __launch_bounds__(256) sgemm_kernel(
    const float* __restrict__ A, const float* __restrict__ Bm,
    const float* __restrict__ bias, float* __restrict__ C,
    int M, int N, int Kd, int relu)
{
    __shared__ float sA[GBK][GBM];
    __shared__ float sB[GBK][GBN];

    int tid = threadIdx.x;
    size_t row0 = (size_t)blockIdx.y * GBM;
    int col0 = blockIdx.x * GBN;

    int tx = tid & 15;          // 0..15, col tile
    int ty = tid >> 4;          // 0..15, row tile

    // A load: 128x8 as float4, thread -> (row=tid/2, col=(tid&1)*4)
    int arow = tid >> 1;
    int acol = (tid & 1) * 4;
    // B load: 8x128 as float4, thread -> (row=tid/32, col=(tid&31)*4)
    int brow = tid >> 5;
    int bcol = (tid & 31) * 4;

    float acc[GTM][GTN] = {};

    for (int k0 = 0; k0 < Kd; k0 += GBK) {
        float4 a4 = *(const float4*)(A + (row0 + arow) * (size_t)Kd + k0 + acol);
        sA[acol + 0][arow] = a4.x;
        sA[acol + 1][arow] = a4.y;
        sA[acol + 2][arow] = a4.z;
        sA[acol + 3][arow] = a4.w;
        float4 b4 = *(const float4*)(Bm + (size_t)(k0 + brow) * N + col0 + bcol);
        *(float4*)&sB[brow][bcol] = b4;
        __syncthreads();

#pragma unroll
        for (int k = 0; k < GBK; k++) {
            float4 ra0 = *(float4*)&sA[k][ty * GTM];
            float4 ra1 = *(float4*)&sA[k][ty * GTM + 4];
            float4 rb0 = *(float4*)&sB[k][tx * GTN];
            float4 rb1 = *(float4*)&sB[k][tx * GTN + 4];
            float ra[GTM] = {ra0.x, ra0.y, ra0.z, ra0.w, ra1.x, ra1.y, ra1.z, ra1.w};
            float rb[GTN] = {rb0.x, rb0.y, rb0.z, rb0.w, rb1.x, rb1.y, rb1.z, rb1.w};
#pragma unroll
            for (int i = 0; i < GTM; i++)
#pragma unroll
                for (int j = 0; j < GTN; j++)
                    acc[i][j] += ra[i] * rb[j];
        }
        __syncthreads();
    }

    float bv[GTN];
#pragma unroll
    for (int j = 0; j < GTN; j++)
        bv[j] = bias ? bias[col0 + tx * GTN + j] : 0.0f;

#pragma unroll
    for (int i = 0; i < GTM; i++) {
        size_t crow = row0 + ty * GTM + i;
#pragma unroll
        for (int j = 0; j < GTN; j++) {
            float v = acc[i][j] + bv[j];
            if (relu) v = fmaxf(v, 0.0f);
            C[crow * (size_t)N + col0 + tx * GTN + j] = v;
        }
    }
}

// ============================================================================
// K3: per-point X-transform, in place: f_all[k][c] = sum_j X[k][j] * f_all[j][c]
//     warp per point, 4 warps / CTA. Stage X + f_all in shared, write back.
// ============================================================================
#define XW 4
__global__ void __launch_bounds__(XW * 32) xform_kernel()
{
    __shared__ float sX[XW][256];
    __shared__ float sF[XW][1536];

    int wid = threadIdx.x >> 5, lane = threadIdx.x & 31;
    size_t p = (size_t)blockIdx.x * XW + wid;

    const float* Xp = d_X + p * 256;
    float* Fp = d_fall + p * 1536;

#pragma unroll
    for (int t = 0; t < 8; t++) sX[wid][lane + 32 * t] = Xp[lane + 32 * t];
#pragma unroll
    for (int t = 0; t < 48; t++) sF[wid][lane + 32 * t] = Fp[lane + 32 * t];
    __syncwarp();

#pragma unroll
    for (int cc = 0; cc < 3; cc++) {
        int c = lane + cc * 32;
        float col[16];
#pragma unroll
        for (int j = 0; j < 16; j++) col[j] = sF[wid][j * 96 + c];
#pragma unroll
        for (int k = 0; k < 16; k++) {
            float acc = 0.0f;
#pragma unroll
            for (int j = 0; j < 16; j++) acc += sX[wid][k * 16 + j] * col[j];
            Fp[k * 96 + c] = acc;   // safe: all reads came from shared copy
        }
    }
}

// ============================================================================
extern "C" void kernel_launch(void* const* d_in, const int* in_sizes, int n_in,
                              void* d_out, int out_size)
{
    const float* coords = (const float*)d_in[0];
    const float* feats  = (const float*)d_in[1];
    const int*   knn    = (const int*)d_in[2];
    const float* Wd     = (const float*)d_in[3];
    const float* bd     = (const float*)d_in[4];
    const float* Wx1    = (const float*)d_in[5];
    const float* bx1    = (const float*)d_in[6];
    const float* Wx2    = (const float*)d_in[7];
    const float* Wconv  = (const float*)d_in[8];
    const float* bconv  = (const float*)d_in[9];
    float* out = (float*)d_out;

    void *p_prel, *p_h, *p_X, *p_fall;
    cudaGetSymbolAddress(&p_prel, d_prel);
    cudaGetSymbolAddress(&p_h,    d_h);
    cudaGetSymbolAddress(&p_X,    d_X);
    cudaGetSymbolAddress(&p_fall, d_fall);

    // K1: gather + prel + f_delta + feats
    gather_kernel<<<NP / 8, 256>>>(coords, feats, knn, Wd, bd);

    // K2a: h = relu(prel @ Wx1 + bx1)   M=NP, N=256, K=48
    {
        dim3 grid(256 / GBN, NP / GBM);
        sgemm_kernel<<<grid, 256>>>((const float*)p_prel, Wx1, bx1,
                                    (float*)p_h, NP, 256, 48, 1);
    }
    // K2b: X = h @ Wx2                  M=NP, N=256, K=256
    {
        dim3 grid(256 / GBN, NP / GBM);
        sgemm_kernel<<<grid, 256>>>((const float*)p_h, Wx2, nullptr,
                                    (float*)p_X, NP, 256, 256, 0);
    }
    // K3: in-place X-transform of f_all
    xform_kernel<<<NP / XW, XW * 32>>>();

    // K4: out = f_all @ Wconv_flat + bconv   M=NP, N=128, K=1536
    {
        dim3 grid(128 / GBN, NP / GBM);
        sgemm_kernel<<<grid, 256>>>((const float*)p_fall, Wconv, bconv,
                                    out, NP, 128, 1536, 0);
    }
}

// round 4
// speedup vs baseline: 1.5685x; 1.5685x over previous
#include <cuda_runtime.h>
#include <cuda_bf16.h>
#include <cstdint>

// Problem constants
#define Bb    4
#define Nn    32768
#define NP    (Bb * Nn)          // 131072 points
#define CIN   64

// -------------------- scratch (allocation-free device globals) --------------
__device__ float d_prel[(size_t)NP * 48];                 // (NP, 3K)
__device__ float d_fall[(size_t)NP * 1536];               // pre-transform f_all fp32
__device__ float d_X[(size_t)NP * 256];                   // X matrices fp32
__device__ __nv_bfloat16 d_h_hi[(size_t)NP * 256];        // h split
__device__ __nv_bfloat16 d_h_lo[(size_t)NP * 256];
__device__ __nv_bfloat16 d_fa_hi[(size_t)NP * 1536];      // transformed f_all split
__device__ __nv_bfloat16 d_fa_lo[(size_t)NP * 1536];
__device__ __nv_bfloat16 d_wt2_hi[256 * 256];             // Wx2^T  [N=256][K=256]
__device__ __nv_bfloat16 d_wt2_lo[256 * 256];
__device__ __nv_bfloat16 d_wtc_hi[128 * 1536];            // Wconv^T [N=128][K=1536]
__device__ __nv_bfloat16 d_wtc_lo[128 * 1536];

__device__ __forceinline__ void split2(float v, __nv_bfloat16& h, __nv_bfloat16& l) {
    h = __float2bfloat16(v);
    l = __float2bfloat16(v - __bfloat162float(h));
}

__device__ __forceinline__ uint32_t smem_u32(const void* p) {
    uint32_t a;
    asm("{ .reg .u64 t; cvta.to.shared.u64 t, %1; cvt.u32.u64 %0, t; }" : "=r"(a) : "l"(p));
    return a;
}

// ============================================================================
// K0: split + transpose weights (Wx2 -> [256][256], Wconv -> [128][1536])
// ============================================================================
__global__ void prep_kernel(const float* __restrict__ Wx2,
                            const float* __restrict__ Wconv) {
    int i = blockIdx.x * 256 + threadIdx.x;
    if (i < 256 * 256) {
        int k = i >> 8, n = i & 255;
        __nv_bfloat16 h, l; split2(Wx2[i], h, l);
        d_wt2_hi[n * 256 + k] = h; d_wt2_lo[n * 256 + k] = l;
    }
    int j = i - 65536;
    if (j >= 0 && j < 1536 * 128) {
        int k = j >> 7, n = j & 127;
        __nv_bfloat16 h, l; split2(Wconv[j], h, l);
        d_wtc_hi[(size_t)n * 1536 + k] = h; d_wtc_lo[(size_t)n * 1536 + k] = l;
    }
}

// ============================================================================
// K1: gather neighbors, compute p_rel, f_delta, stage f_all (pre-transform)
// ============================================================================
__global__ void __launch_bounds__(256) gather_kernel(
    const float* __restrict__ coords, const float* __restrict__ feats,
    const int* __restrict__ knn, const float* __restrict__ Wd,
    const float* __restrict__ bd)
{
    __shared__ float sWd[96];
    __shared__ float sbd[32];
    __shared__ int   snb[8][16];

    int tid = threadIdx.x;
    if (tid < 96) sWd[tid] = Wd[tid];
    if (tid < 32) sbd[tid] = bd[tid];
    __syncthreads();

    int wid = tid >> 5, lane = tid & 31;
    size_t p = (size_t)blockIdx.x * 8 + wid;
    int b = (int)(p >> 15);

    float cx = coords[p * 3 + 0];
    float cy = coords[p * 3 + 1];
    float cz = coords[p * 3 + 2];

    if (lane < 16) {
        int nb = knn[p * 16 + lane];
        snb[wid][lane] = nb;
        size_t q = ((size_t)b * Nn + nb) * 3;
        float prx = coords[q + 0] - cx;
        float pry = coords[q + 1] - cy;
        float prz = coords[q + 2] - cz;
        float* pf = d_prel + p * 48 + lane * 3;
        pf[0] = prx; pf[1] = pry; pf[2] = prz;
        float* gout = d_fall + p * 1536 + (size_t)lane * 96;
#pragma unroll
        for (int c = 0; c < 32; c++) {
            float v = sbd[c] + prx * sWd[c] + pry * sWd[32 + c] + prz * sWd[64 + c];
            gout[c] = fmaxf(v, 0.0f);
        }
    }
    __syncwarp();

    size_t fb = (size_t)b * Nn * CIN;
    float* gbase = d_fall + p * 1536;
#pragma unroll
    for (int j = 0; j < 16; j++) {
        int nb = snb[wid][j];
        const float* fr = feats + fb + (size_t)nb * CIN;
        gbase[j * 96 + 32 + lane] = fr[lane];
        gbase[j * 96 + 64 + lane] = fr[32 + lane];
    }
}

// ============================================================================
// K2a: fp32 SGEMM  h = relu(prel @ Wx1 + bx1), emits hi/lo bf16 split of h
// ============================================================================
#define GBM 128
#define GBN 128
#define GBK 8
#define GTM 8
#define GTN 8

__global__ void __launch_bounds__(256) sgemm_hsplit_kernel(
    const float* __restrict__ A, const float* __restrict__ Bm,
    const float* __restrict__ bias,
    __nv_bfloat16* __restrict__ Ch, __nv_bfloat16* __restrict__ Cl,
    int N, int Kd)
{
    __shared__ float sA[GBK][GBM];
    __shared__ float sB[GBK][GBN];

    int tid = threadIdx.x;
    size_t row0 = (size_t)blockIdx.y * GBM;
    int col0 = blockIdx.x * GBN;

    int tx = tid & 15;
    int ty = tid >> 4;
    int arow = tid >> 1;
    int acol = (tid & 1) * 4;
    int brow = tid >> 5;
    int bcol = (tid & 31) * 4;

    float acc[GTM][GTN] = {};

    for (int k0 = 0; k0 < Kd; k0 += GBK) {
        float4 a4 = *(const float4*)(A + (row0 + arow) * (size_t)Kd + k0 + acol);
        sA[acol + 0][arow] = a4.x;
        sA[acol + 1][arow] = a4.y;
        sA[acol + 2][arow] = a4.z;
        sA[acol + 3][arow] = a4.w;
        float4 b4 = *(const float4*)(Bm + (size_t)(k0 + brow) * N + col0 + bcol);
        *(float4*)&sB[brow][bcol] = b4;
        __syncthreads();

#pragma unroll
        for (int k = 0; k < GBK; k++) {
            float4 ra0 = *(float4*)&sA[k][ty * GTM];
            float4 ra1 = *(float4*)&sA[k][ty * GTM + 4];
            float4 rb0 = *(float4*)&sB[k][tx * GTN];
            float4 rb1 = *(float4*)&sB[k][tx * GTN + 4];
            float ra[GTM] = {ra0.x, ra0.y, ra0.z, ra0.w, ra1.x, ra1.y, ra1.z, ra1.w};
            float rb[GTN] = {rb0.x, rb0.y, rb0.z, rb0.w, rb1.x, rb1.y, rb1.z, rb1.w};
#pragma unroll
            for (int i = 0; i < GTM; i++)
#pragma unroll
                for (int j = 0; j < GTN; j++)
                    acc[i][j] += ra[i] * rb[j];
        }
        __syncthreads();
    }

    float bv[GTN];
#pragma unroll
    for (int j = 0; j < GTN; j++) bv[j] = bias[col0 + tx * GTN + j];

#pragma unroll
    for (int i = 0; i < GTM; i++) {
        size_t crow = row0 + ty * GTM + i;
#pragma unroll
        for (int j = 0; j < GTN; j++) {
            float v = fmaxf(acc[i][j] + bv[j], 0.0f);
            __nv_bfloat16 h, l; split2(v, h, l);
            size_t idx = crow * (size_t)N + col0 + tx * GTN + j;
            Ch[idx] = h;
            Cl[idx] = l;
        }
    }
}

// ============================================================================
// K3: per-point X-transform; reads fp32 f_all + X, writes hi/lo bf16 split
// ============================================================================
#define XW 4
__global__ void __launch_bounds__(XW * 32) xform_kernel()
{
    __shared__ float sX[XW][256];
    __shared__ float sF[XW][1536];

    int wid = threadIdx.x >> 5, lane = threadIdx.x & 31;
    size_t p = (size_t)blockIdx.x * XW + wid;

    const float* Xp = d_X + p * 256;
    const float* Fp = d_fall + p * 1536;
    __nv_bfloat16* Oh = d_fa_hi + p * 1536;
    __nv_bfloat16* Ol = d_fa_lo + p * 1536;

#pragma unroll
    for (int t = 0; t < 8; t++) sX[wid][lane + 32 * t] = Xp[lane + 32 * t];
#pragma unroll
    for (int t = 0; t < 48; t++) sF[wid][lane + 32 * t] = Fp[lane + 32 * t];
    __syncwarp();

#pragma unroll
    for (int cc = 0; cc < 3; cc++) {
        int c = lane + cc * 32;
        float col[16];
#pragma unroll
        for (int j = 0; j < 16; j++) col[j] = sF[wid][j * 96 + c];
#pragma unroll
        for (int k = 0; k < 16; k++) {
            float acc = 0.0f;
#pragma unroll
            for (int j = 0; j < 16; j++) acc += sX[wid][k * 16 + j] * col[j];
            __nv_bfloat16 h, l; split2(acc, h, l);
            Oh[k * 96 + c] = h;
            Ol[k * 96 + c] = l;
        }
    }
}

// ============================================================================
// mma.sync bf16 split GEMM:  C(Mx[ldc slice]) = A(M,K) @ B^T(N,K) [+bias]
// A as hi/lo bf16 [M,K] row-major; B as hi/lo bf16 [N,K] row-major (K-major).
// 128x128 CTA tile, BK=32, cp.async double buffer, 8 warps (2x4),
// warp tile 64x32, mma.m16n8k16, 3 passes (AhBh + AlBh + AhBl) in fp32.
// ============================================================================
#define MPITCH 80                    // bytes per SMEM tile row (32 halves + pad)
#define MTILEB (128 * MPITCH)        // 10240 B per operand tile
#define MSTAGE (4 * MTILEB)          // 40960 B per stage (Ah,Al,Bh,Bl)
#define MMA_SMEM (2 * MSTAGE)        // 81920 B

#define CP16(sp, gp) asm volatile("cp.async.cg.shared.global [%0], [%1], 16;" :: "r"(sp), "l"(gp))
#define CP_COMMIT()  asm volatile("cp.async.commit_group;" ::: "memory")
#define CP_WAIT1()   asm volatile("cp.async.wait_group 1;" ::: "memory")

#define LDSM_X4(r0, r1, r2, r3, a) \
    asm volatile("ldmatrix.sync.aligned.m8n8.x4.shared.b16 {%0,%1,%2,%3}, [%4];" \
        : "=r"(r0), "=r"(r1), "=r"(r2), "=r"(r3) : "r"(a))
#define LDSM_X2(r0, r1, a) \
    asm volatile("ldmatrix.sync.aligned.m8n8.x2.shared.b16 {%0,%1}, [%2];" \
        : "=r"(r0), "=r"(r1) : "r"(a))
#define MMA16816(c, a, b) \
    asm volatile("mma.sync.aligned.m16n8k16.row.col.f32.bf16.bf16.f32 " \
        "{%0,%1,%2,%3}, {%4,%5,%6,%7}, {%8,%9}, {%0,%1,%2,%3};" \
        : "+f"((c)[0]), "+f"((c)[1]), "+f"((c)[2]), "+f"((c)[3]) \
        : "r"((a)[0]), "r"((a)[1]), "r"((a)[2]), "r"((a)[3]), "r"((b)[0]), "r"((b)[1]))

__device__ __forceinline__ void cp_tile(uint32_t sbase, const __nv_bfloat16* __restrict__ g,
                                        size_t row0, int Kd, int k0)
{
    int tid = threadIdx.x;
#pragma unroll
    for (int t = 0; t < 2; t++) {
        int idx = tid + t * 256;        // 0..511
        int row = idx >> 2;
        int c = idx & 3;
        const void* gp = g + (row0 + row) * (size_t)Kd + k0 + c * 8;
        uint32_t sp = sbase + row * MPITCH + c * 16;
        CP16(sp, gp);
    }
}

__global__ void __launch_bounds__(256) mma_gemm_kernel(
    const __nv_bfloat16* __restrict__ Ah, const __nv_bfloat16* __restrict__ Al,
    const __nv_bfloat16* __restrict__ Bh, const __nv_bfloat16* __restrict__ Bl,
    float* __restrict__ C, const float* __restrict__ bias, int Kd, int ldc)
{
    extern __shared__ char smem[];
    uint32_t sb = smem_u32(smem);
    int tid = threadIdx.x, wid = tid >> 5, lane = tid & 31;
    int wr = wid >> 2;                   // 0..1 warp row
    int wc = wid & 3;                    // 0..3 warp col
    size_t row0 = (size_t)blockIdx.y * 128;
    int col0 = blockIdx.x * 128;

    const int NC = Kd >> 5;              // BK = 32

    // prologue: stages 0, 1
#pragma unroll
    for (int s = 0; s < 2; s++) {
        uint32_t st = sb + s * MSTAGE;
        int k0 = s << 5;
        cp_tile(st,              Ah, row0,         Kd, k0);
        cp_tile(st + MTILEB,     Al, row0,         Kd, k0);
        cp_tile(st + 2 * MTILEB, Bh, (size_t)col0, Kd, k0);
        cp_tile(st + 3 * MTILEB, Bl, (size_t)col0, Kd, k0);
        CP_COMMIT();
    }

    float acc[4][4][4] = {};             // [mt][nt][frag]

    // per-lane ldmatrix address offsets (within a tile, per k-step)
    uint32_t a_lrow = (uint32_t)(lane & 15) * MPITCH + (uint32_t)(lane >> 4) * 16;
    uint32_t b_lrow = (uint32_t)(lane & 7) * MPITCH + (uint32_t)((lane >> 3) & 1) * 16;

    for (int c = 0; c < NC; c++) {
        CP_WAIT1();
        __syncthreads();

        uint32_t st = sb + (c & 1) * MSTAGE;
        uint32_t a_base  = st + (uint32_t)(wr * 64) * MPITCH + a_lrow;
        uint32_t b_base  = st + 2 * MTILEB + (uint32_t)(wc * 32) * MPITCH + b_lrow;

#pragma unroll
        for (int ks = 0; ks < 2; ks++) {
            uint32_t koff = ks * 32;     // 16 halves = 32 bytes
            uint32_t af[4][4], tf[4][4];
            uint32_t bh[4][2], bl[4][2];
#pragma unroll
            for (int mt = 0; mt < 4; mt++)
                LDSM_X4(af[mt][0], af[mt][1], af[mt][2], af[mt][3],
                        a_base + mt * 16 * MPITCH + koff);
#pragma unroll
            for (int nt = 0; nt < 4; nt++)
                LDSM_X2(bh[nt][0], bh[nt][1], b_base + nt * 8 * MPITCH + koff);
#pragma unroll
            for (int mt = 0; mt < 4; mt++)
#pragma unroll
                for (int nt = 0; nt < 4; nt++)
                    MMA16816(acc[mt][nt], af[mt], bh[nt]);
            // Al * Bh
#pragma unroll
            for (int mt = 0; mt < 4; mt++)
                LDSM_X4(tf[mt][0], tf[mt][1], tf[mt][2], tf[mt][3],
                        a_base + MTILEB + mt * 16 * MPITCH + koff);
#pragma unroll
            for (int mt = 0; mt < 4; mt++)
#pragma unroll
                for (int nt = 0; nt < 4; nt++)
                    MMA16816(acc[mt][nt], tf[mt], bh[nt]);
            // Ah * Bl
#pragma unroll
            for (int nt = 0; nt < 4; nt++)
                LDSM_X2(bl[nt][0], bl[nt][1], b_base + MTILEB + nt * 8 * MPITCH + koff);
#pragma unroll
            for (int mt = 0; mt < 4; mt++)
#pragma unroll
                for (int nt = 0; nt < 4; nt++)
                    MMA16816(acc[mt][nt], af[mt], bl[nt]);
        }
        __syncthreads();

        if (c + 2 < NC) {
            uint32_t sn = sb + (c & 1) * MSTAGE;
            int k0 = (c + 2) << 5;
            cp_tile(sn,              Ah, row0,         Kd, k0);
            cp_tile(sn + MTILEB,     Al, row0,         Kd, k0);
            cp_tile(sn + 2 * MTILEB, Bh, (size_t)col0, Kd, k0);
            cp_tile(sn + 3 * MTILEB, Bl, (size_t)col0, Kd, k0);
        }
        CP_COMMIT();                      // commit every iter for stable accounting
    }

    // epilogue
#pragma unroll
    for (int mt = 0; mt < 4; mt++) {
        size_t r = row0 + wr * 64 + mt * 16 + (lane >> 2);
#pragma unroll
        for (int nt = 0; nt < 4; nt++) {
            int cc = col0 + wc * 32 + nt * 8 + (lane & 3) * 2;
            float bx = bias ? bias[cc] : 0.0f;
            float by = bias ? bias[cc + 1] : 0.0f;
            float2 v0 = {acc[mt][nt][0] + bx, acc[mt][nt][1] + by};
            float2 v1 = {acc[mt][nt][2] + bx, acc[mt][nt][3] + by};
            *(float2*)(C + r * (size_t)ldc + cc) = v0;
            *(float2*)(C + (r + 8) * (size_t)ldc + cc) = v1;
        }
    }
}

// ============================================================================
extern "C" void kernel_launch(void* const* d_in, const int* in_sizes, int n_in,
                              void* d_out, int out_size)
{
    const float* coords = (const float*)d_in[0];
    const float* feats  = (const float*)d_in[1];
    const int*   knn    = (const int*)d_in[2];
    const float* Wd     = (const float*)d_in[3];
    const float* bd     = (const float*)d_in[4];
    const float* Wx1    = (const float*)d_in[5];
    const float* bx1    = (const float*)d_in[6];
    const float* Wx2    = (const float*)d_in[7];
    const float* Wconv  = (const float*)d_in[8];
    const float* bconv  = (const float*)d_in[9];
    float* out = (float*)d_out;

    void *p_prel, *p_X, *p_hh, *p_hl, *p_fh, *p_fl;
    void *p_w2h, *p_w2l, *p_wch, *p_wcl;
    cudaGetSymbolAddress(&p_prel, d_prel);
    cudaGetSymbolAddress(&p_X,    d_X);
    cudaGetSymbolAddress(&p_hh,   d_h_hi);
    cudaGetSymbolAddress(&p_hl,   d_h_lo);
    cudaGetSymbolAddress(&p_fh,   d_fa_hi);
    cudaGetSymbolAddress(&p_fl,   d_fa_lo);
    cudaGetSymbolAddress(&p_w2h,  d_wt2_hi);
    cudaGetSymbolAddress(&p_w2l,  d_wt2_lo);
    cudaGetSymbolAddress(&p_wch,  d_wtc_hi);
    cudaGetSymbolAddress(&p_wcl,  d_wtc_lo);

    cudaFuncSetAttribute(mma_gemm_kernel,
                         cudaFuncAttributeMaxDynamicSharedMemorySize, MMA_SMEM);

    // K0: weight transpose + split
    prep_kernel<<<1024, 256>>>(Wx2, Wconv);

    // K1: gather + prel + f_delta + feats
    gather_kernel<<<NP / 8, 256>>>(coords, feats, knn, Wd, bd);

    // K2a: h = relu(prel @ Wx1 + bx1) -> hi/lo split   (M=NP, N=256, K=48)
    {
        dim3 grid(256 / GBN, NP / GBM);
        sgemm_hsplit_kernel<<<grid, 256>>>((const float*)p_prel, Wx1, bx1,
                                           (__nv_bfloat16*)p_hh, (__nv_bfloat16*)p_hl,
                                           256, 48);
    }

    // K2b: X = h @ Wx2   (mma.sync, M=NP, N=256, K=256)
    {
        dim3 grid(2, NP / 128);
        mma_gemm_kernel<<<grid, 256, MMA_SMEM>>>(
            (const __nv_bfloat16*)p_hh, (const __nv_bfloat16*)p_hl,
            (const __nv_bfloat16*)p_w2h, (const __nv_bfloat16*)p_w2l,
            (float*)p_X, nullptr, 256, 256);
    }

    // K3: X-transform, emits hi/lo bf16 f_all
    xform_kernel<<<NP / XW, XW * 32>>>();

    // K4: out = f_all @ Wconv + bconv   (mma.sync, M=NP, N=128, K=1536)
    {
        dim3 grid(1, NP / 128);
        mma_gemm_kernel<<<grid, 256, MMA_SMEM>>>(
            (const __nv_bfloat16*)p_fh, (const __nv_bfloat16*)p_fl,
            (const __nv_bfloat16*)p_wch, (const __nv_bfloat16*)p_wcl,
            out, bconv, 1536, 128);
    }
}

// round 6
// speedup vs baseline: 1.6972x; 1.0820x over previous
#include <cuda_runtime.h>
#include <cuda_bf16.h>
#include <cstdint>

// Problem constants
#define Bb    4
#define Nn    32768
#define NP    (Bb * Nn)          // 131072 points
#define CIN   64

// -------------------- scratch (allocation-free device globals) --------------
__device__ float d_X[(size_t)NP * 256];                   // X matrices fp32
__device__ __nv_bfloat16 d_prel_hi[(size_t)NP * 64];      // prel, K padded 48->64
__device__ __nv_bfloat16 d_prel_lo[(size_t)NP * 64];
__device__ __nv_bfloat16 d_h_hi[(size_t)NP * 256];        // h split
__device__ __nv_bfloat16 d_h_lo[(size_t)NP * 256];
__device__ __nv_bfloat16 d_fa_hi[(size_t)NP * 1536];      // transformed f_all split
__device__ __nv_bfloat16 d_fa_lo[(size_t)NP * 1536];
__device__ __nv_bfloat16 d_wt1_hi[256 * 64];              // Wx1^T  [N=256][K=64 pad]
__device__ __nv_bfloat16 d_wt1_lo[256 * 64];
__device__ __nv_bfloat16 d_wt2_hi[256 * 256];             // Wx2^T  [N=256][K=256]
__device__ __nv_bfloat16 d_wt2_lo[256 * 256];
__device__ __nv_bfloat16 d_wtc_hi[128 * 1536];            // Wconv^T [N=128][K=1536]
__device__ __nv_bfloat16 d_wtc_lo[128 * 1536];

__device__ __forceinline__ void split2(float v, __nv_bfloat16& h, __nv_bfloat16& l) {
    h = __float2bfloat16(v);
    l = __float2bfloat16(v - __bfloat162float(h));
}

__device__ __forceinline__ uint32_t smem_u32(const void* p) {
    uint32_t a;
    asm("{ .reg .u64 t; cvta.to.shared.u64 t, %1; cvt.u32.u64 %0, t; }" : "=r"(a) : "l"(p));
    return a;
}

// ============================================================================
// K0: split + transpose weights
// ============================================================================
__global__ void prep_kernel(const float* __restrict__ Wx1,
                            const float* __restrict__ Wx2,
                            const float* __restrict__ Wconv) {
    int i = blockIdx.x * 256 + threadIdx.x;
    if (i < 256 * 256) {
        int k = i >> 8, n = i & 255;
        __nv_bfloat16 h, l; split2(Wx2[i], h, l);
        d_wt2_hi[n * 256 + k] = h; d_wt2_lo[n * 256 + k] = l;
    }
    int j = i - 65536;
    if (j >= 0 && j < 1536 * 128) {
        int k = j >> 7, n = j & 127;
        __nv_bfloat16 h, l; split2(Wconv[j], h, l);
        d_wtc_hi[(size_t)n * 1536 + k] = h; d_wtc_lo[(size_t)n * 1536 + k] = l;
    }
    if (i < 256 * 64) {                   // Wx1^T padded: slot i = n*64+k
        int n = i >> 6, k = i & 63;
        float v = (k < 48) ? Wx1[k * 256 + n] : 0.0f;
        __nv_bfloat16 h, l; split2(v, h, l);
        d_wt1_hi[i] = h; d_wt1_lo[i] = l;
    }
}

// ============================================================================
// K1: prel (hi/lo bf16, zero-padded to K=64). 16 threads per point.
// ============================================================================
__global__ void __launch_bounds__(256) prel_kernel(
    const float* __restrict__ coords, const int* __restrict__ knn)
{
    int tid = threadIdx.x;
    size_t p = (size_t)blockIdx.x * 16 + (tid >> 4);
    int k = tid & 15;
    int b = (int)(p >> 15);

    float cx = coords[p * 3 + 0];
    float cy = coords[p * 3 + 1];
    float cz = coords[p * 3 + 2];
    int nb = knn[p * 16 + k];
    size_t q = ((size_t)b * Nn + nb) * 3;
    float r0 = coords[q + 0] - cx;
    float r1 = coords[q + 1] - cy;
    float r2 = coords[q + 2] - cz;

    size_t base = p * 64 + k * 3;
    __nv_bfloat16 h, l;
    split2(r0, h, l); d_prel_hi[base + 0] = h; d_prel_lo[base + 0] = l;
    split2(r1, h, l); d_prel_hi[base + 1] = h; d_prel_lo[base + 1] = l;
    split2(r2, h, l); d_prel_hi[base + 2] = h; d_prel_lo[base + 2] = l;
    // zero pad cols 48..63
    d_prel_hi[p * 64 + 48 + k] = __float2bfloat16(0.0f);
    d_prel_lo[p * 64 + 48 + k] = __float2bfloat16(0.0f);
}

// ============================================================================
// K3: fused gather + f_delta + X-transform -> fa hi/lo.  Warp per point.
// ============================================================================
#define FW 4
__global__ void __launch_bounds__(FW * 32) fused_xform_kernel(
    const float* __restrict__ coords, const float* __restrict__ feats,
    const int* __restrict__ knn, const float* __restrict__ Wd,
    const float* __restrict__ bd)
{
    __shared__ float sWd[96];
    __shared__ float sbd[32];
    __shared__ float sX[FW][256];
    __shared__ float sF[FW][1536];
    __shared__ int   snb[FW][16];

    int tid = threadIdx.x;
    if (tid < 96) sWd[tid] = Wd[tid];
    if (tid < 32) sbd[tid] = bd[tid];
    __syncthreads();

    int wid = tid >> 5, lane = tid & 31;
    size_t p = (size_t)blockIdx.x * FW + wid;
    int b = (int)(p >> 15);

    const float* Xp = d_X + p * 256;
#pragma unroll
    for (int t = 0; t < 8; t++) sX[wid][lane + 32 * t] = Xp[lane + 32 * t];

    float cx = coords[p * 3 + 0];
    float cy = coords[p * 3 + 1];
    float cz = coords[p * 3 + 2];

    if (lane < 16) {
        int nb = knn[p * 16 + lane];
        snb[wid][lane] = nb;
        size_t q = ((size_t)b * Nn + nb) * 3;
        float prx = coords[q + 0] - cx;
        float pry = coords[q + 1] - cy;
        float prz = coords[q + 2] - cz;
#pragma unroll
        for (int c = 0; c < 32; c++) {
            float v = sbd[c] + prx * sWd[c] + pry * sWd[32 + c] + prz * sWd[64 + c];
            sF[wid][lane * 96 + c] = fmaxf(v, 0.0f);
        }
    }
    __syncwarp();

    size_t fb = (size_t)b * Nn * CIN;
#pragma unroll
    for (int j = 0; j < 16; j++) {
        int nb = snb[wid][j];
        const float* fr = feats + fb + (size_t)nb * CIN;
        sF[wid][j * 96 + 32 + lane] = fr[lane];
        sF[wid][j * 96 + 64 + lane] = fr[32 + lane];
    }
    __syncwarp();

    __nv_bfloat16* Oh = d_fa_hi + p * 1536;
    __nv_bfloat16* Ol = d_fa_lo + p * 1536;
#pragma unroll
    for (int cc = 0; cc < 3; cc++) {
        int c = lane + cc * 32;
        float col[16];
#pragma unroll
        for (int j = 0; j < 16; j++) col[j] = sF[wid][j * 96 + c];
#pragma unroll
        for (int k = 0; k < 16; k++) {
            float acc = 0.0f;
#pragma unroll
            for (int j = 0; j < 16; j++) acc += sX[wid][k * 16 + j] * col[j];
            __nv_bfloat16 h, l; split2(acc, h, l);
            Oh[k * 96 + c] = h;
            Ol[k * 96 + c] = l;
        }
    }
}

// ============================================================================
// mma.sync bf16 split GEMM:  C(Mx[ldc slice]) = A(M,K) @ B^T(N,K) [+bias]
// 128x128 CTA tile, BK=32, cp.async double buffer, 8 warps (2x4),
// warp tile 64x32, mma.m16n8k16, 3 passes (AhBh + AhBl + AlBh) in fp32.
// MODE 0: C fp32 (+bias if non-null).  MODE 1: relu(+bias) -> bf16 hi/lo split.
// ============================================================================
#define MPITCH 80                    // bytes per SMEM tile row (32 halves + pad)
#define MTILEB (128 * MPITCH)        // 10240 B per operand tile
#define MSTAGE (4 * MTILEB)          // 40960 B per stage (Ah,Al,Bh,Bl)
#define MMA_SMEM (2 * MSTAGE)        // 81920 B

#define CP16(sp, gp) asm volatile("cp.async.cg.shared.global [%0], [%1], 16;" :: "r"(sp), "l"(gp))
#define CP_COMMIT()  asm volatile("cp.async.commit_group;" ::: "memory")
#define CP_WAIT1()   asm volatile("cp.async.wait_group 1;" ::: "memory")

#define LDSM_X4(r0, r1, r2, r3, a) \
    asm volatile("ldmatrix.sync.aligned.m8n8.x4.shared.b16 {%0,%1,%2,%3}, [%4];" \
        : "=r"(r0), "=r"(r1), "=r"(r2), "=r"(r3) : "r"(a))
#define LDSM_X2(r0, r1, a) \
    asm volatile("ldmatrix.sync.aligned.m8n8.x2.shared.b16 {%0,%1}, [%2];" \
        : "=r"(r0), "=r"(r1) : "r"(a))
#define MMA16816(c, a, b) \
    asm volatile("mma.sync.aligned.m16n8k16.row.col.f32.bf16.bf16.f32 " \
        "{%0,%1,%2,%3}, {%4,%5,%6,%7}, {%8,%9}, {%0,%1,%2,%3};" \
        : "+f"((c)[0]), "+f"((c)[1]), "+f"((c)[2]), "+f"((c)[3]) \
        : "r"((a)[0]), "r"((a)[1]), "r"((a)[2]), "r"((a)[3]), "r"((b)[0]), "r"((b)[1]))

__device__ __forceinline__ void cp_tile(uint32_t sbase, const __nv_bfloat16* __restrict__ g,
                                        size_t row0, int Kd, int k0)
{
    int tid = threadIdx.x;
#pragma unroll
    for (int t = 0; t < 2; t++) {
        int idx = tid + t * 256;        // 0..511
        int row = idx >> 2;
        int c = idx & 3;
        const void* gp = g + (row0 + row) * (size_t)Kd + k0 + c * 8;
        uint32_t sp = sbase + row * MPITCH + c * 16;
        CP16(sp, gp);
    }
}

template <int MODE>
__global__ void __launch_bounds__(256, 2) mma_gemm_kernel(
    const __nv_bfloat16* __restrict__ Ah, const __nv_bfloat16* __restrict__ Al,
    const __nv_bfloat16* __restrict__ Bh, const __nv_bfloat16* __restrict__ Bl,
    float* __restrict__ C, __nv_bfloat16* __restrict__ Ch,
    __nv_bfloat16* __restrict__ Cl,
    const float* __restrict__ bias, int Kd, int ldc)
{
    extern __shared__ char smem[];
    uint32_t sb = smem_u32(smem);
    int tid = threadIdx.x, wid = tid >> 5, lane = tid & 31;
    int wr = wid >> 2;                   // 0..1 warp row
    int wc = wid & 3;                    // 0..3 warp col
    size_t row0 = (size_t)blockIdx.y * 128;
    int col0 = blockIdx.x * 128;

    const int NC = Kd >> 5;              // BK = 32

    // prologue: stages 0, 1
#pragma unroll
    for (int s = 0; s < 2; s++) {
        uint32_t st = sb + s * MSTAGE;
        int k0 = s << 5;
        cp_tile(st,              Ah, row0,         Kd, k0);
        cp_tile(st + MTILEB,     Al, row0,         Kd, k0);
        cp_tile(st + 2 * MTILEB, Bh, (size_t)col0, Kd, k0);
        cp_tile(st + 3 * MTILEB, Bl, (size_t)col0, Kd, k0);
        CP_COMMIT();
    }

    float acc[4][4][4] = {};             // [mt][nt][frag]

    uint32_t a_lrow = (uint32_t)(lane & 15) * MPITCH + (uint32_t)(lane >> 4) * 16;
    uint32_t b_lrow = (uint32_t)(lane & 7) * MPITCH + (uint32_t)((lane >> 3) & 1) * 16;

    for (int c = 0; c < NC; c++) {
        CP_WAIT1();
        __syncthreads();

        uint32_t st = sb + (c & 1) * MSTAGE;
        uint32_t a_base  = st + (uint32_t)(wr * 64) * MPITCH + a_lrow;
        uint32_t b_base  = st + 2 * MTILEB + (uint32_t)(wc * 32) * MPITCH + b_lrow;

#pragma unroll
        for (int ks = 0; ks < 2; ks++) {
            uint32_t koff = ks * 32;     // 16 halves = 32 bytes
            uint32_t af[4][4];
            uint32_t bh[4][2], bl[4][2];
            // pass 1: Ah * Bh
#pragma unroll
            for (int mt = 0; mt < 4; mt++)
                LDSM_X4(af[mt][0], af[mt][1], af[mt][2], af[mt][3],
                        a_base + mt * 16 * MPITCH + koff);
#pragma unroll
            for (int nt = 0; nt < 4; nt++)
                LDSM_X2(bh[nt][0], bh[nt][1], b_base + nt * 8 * MPITCH + koff);
#pragma unroll
            for (int mt = 0; mt < 4; mt++)
#pragma unroll
                for (int nt = 0; nt < 4; nt++)
                    MMA16816(acc[mt][nt], af[mt], bh[nt]);
            // pass 2: Ah * Bl
#pragma unroll
            for (int nt = 0; nt < 4; nt++)
                LDSM_X2(bl[nt][0], bl[nt][1], b_base + MTILEB + nt * 8 * MPITCH + koff);
#pragma unroll
            for (int mt = 0; mt < 4; mt++)
#pragma unroll
                for (int nt = 0; nt < 4; nt++)
                    MMA16816(acc[mt][nt], af[mt], bl[nt]);
            // pass 3: Al * Bh (reuse af registers)
#pragma unroll
            for (int mt = 0; mt < 4; mt++)
                LDSM_X4(af[mt][0], af[mt][1], af[mt][2], af[mt][3],
                        a_base + MTILEB + mt * 16 * MPITCH + koff);
#pragma unroll
            for (int mt = 0; mt < 4; mt++)
#pragma unroll
                for (int nt = 0; nt < 4; nt++)
                    MMA16816(acc[mt][nt], af[mt], bh[nt]);
        }
        __syncthreads();

        if (c + 2 < NC) {
            uint32_t sn = sb + (c & 1) * MSTAGE;
            int k0 = (c + 2) << 5;
            cp_tile(sn,              Ah, row0,         Kd, k0);
            cp_tile(sn + MTILEB,     Al, row0,         Kd, k0);
            cp_tile(sn + 2 * MTILEB, Bh, (size_t)col0, Kd, k0);
            cp_tile(sn + 3 * MTILEB, Bl, (size_t)col0, Kd, k0);
        }
        CP_COMMIT();
    }

    // epilogue
#pragma unroll
    for (int mt = 0; mt < 4; mt++) {
        size_t r = row0 + wr * 64 + mt * 16 + (lane >> 2);
#pragma unroll
        for (int nt = 0; nt < 4; nt++) {
            int cc = col0 + wc * 32 + nt * 8 + (lane & 3) * 2;
            if (MODE == 0) {
                float bx = bias ? bias[cc] : 0.0f;
                float by = bias ? bias[cc + 1] : 0.0f;
                float2 v0 = {acc[mt][nt][0] + bx, acc[mt][nt][1] + by};
                float2 v1 = {acc[mt][nt][2] + bx, acc[mt][nt][3] + by};
                *(float2*)(C + r * (size_t)ldc + cc) = v0;
                *(float2*)(C + (r + 8) * (size_t)ldc + cc) = v1;
            } else {
                float bx = bias[cc];
                float by = bias[cc + 1];
                float v00 = fmaxf(acc[mt][nt][0] + bx, 0.0f);
                float v01 = fmaxf(acc[mt][nt][1] + by, 0.0f);
                float v10 = fmaxf(acc[mt][nt][2] + bx, 0.0f);
                float v11 = fmaxf(acc[mt][nt][3] + by, 0.0f);
                __nv_bfloat16 h0, l0, h1, l1;
                split2(v00, h0, l0); split2(v01, h1, l1);
                *(__nv_bfloat162*)(Ch + r * (size_t)ldc + cc) = __halves2bfloat162(h0, h1);
                *(__nv_bfloat162*)(Cl + r * (size_t)ldc + cc) = __halves2bfloat162(l0, l1);
                split2(v10, h0, l0); split2(v11, h1, l1);
                *(__nv_bfloat162*)(Ch + (r + 8) * (size_t)ldc + cc) = __halves2bfloat162(h0, h1);
                *(__nv_bfloat162*)(Cl + (r + 8) * (size_t)ldc + cc) = __halves2bfloat162(l0, l1);
            }
        }
    }
}

// ============================================================================
extern "C" void kernel_launch(void* const* d_in, const int* in_sizes, int n_in,
                              void* d_out, int out_size)
{
    const float* coords = (const float*)d_in[0];
    const float* feats  = (const float*)d_in[1];
    const int*   knn    = (const int*)d_in[2];
    const float* Wd     = (const float*)d_in[3];
    const float* bd     = (const float*)d_in[4];
    const float* Wx1    = (const float*)d_in[5];
    const float* bx1    = (const float*)d_in[6];
    const float* Wx2    = (const float*)d_in[7];
    const float* Wconv  = (const float*)d_in[8];
    const float* bconv  = (const float*)d_in[9];
    float* out = (float*)d_out;

    void *p_X, *p_ph, *p_pl, *p_hh, *p_hl, *p_fh, *p_fl;
    void *p_w1h, *p_w1l, *p_w2h, *p_w2l, *p_wch, *p_wcl;
    cudaGetSymbolAddress(&p_X,   d_X);
    cudaGetSymbolAddress(&p_ph,  d_prel_hi);
    cudaGetSymbolAddress(&p_pl,  d_prel_lo);
    cudaGetSymbolAddress(&p_hh,  d_h_hi);
    cudaGetSymbolAddress(&p_hl,  d_h_lo);
    cudaGetSymbolAddress(&p_fh,  d_fa_hi);
    cudaGetSymbolAddress(&p_fl,  d_fa_lo);
    cudaGetSymbolAddress(&p_w1h, d_wt1_hi);
    cudaGetSymbolAddress(&p_w1l, d_wt1_lo);
    cudaGetSymbolAddress(&p_w2h, d_wt2_hi);
    cudaGetSymbolAddress(&p_w2l, d_wt2_lo);
    cudaGetSymbolAddress(&p_wch, d_wtc_hi);
    cudaGetSymbolAddress(&p_wcl, d_wtc_lo);

    cudaFuncSetAttribute(mma_gemm_kernel<0>,
                         cudaFuncAttributeMaxDynamicSharedMemorySize, MMA_SMEM);
    cudaFuncSetAttribute(mma_gemm_kernel<1>,
                         cudaFuncAttributeMaxDynamicSharedMemorySize, MMA_SMEM);

    // K0: weight transpose + split
    prep_kernel<<<1024, 256>>>(Wx1, Wx2, Wconv);

    // K1: prel hi/lo (K padded to 64)
    prel_kernel<<<NP / 16, 256>>>(coords, knn);

    // K2a: h = relu(prel @ Wx1 + bx1) -> bf16 hi/lo   (M=NP, N=256, K=64)
    {
        dim3 grid(2, NP / 128);
        mma_gemm_kernel<1><<<grid, 256, MMA_SMEM>>>(
            (const __nv_bfloat16*)p_ph, (const __nv_bfloat16*)p_pl,
            (const __nv_bfloat16*)p_w1h, (const __nv_bfloat16*)p_w1l,
            nullptr, (__nv_bfloat16*)p_hh, (__nv_bfloat16*)p_hl,
            bx1, 64, 256);
    }

    // K2b: X = h @ Wx2   (M=NP, N=256, K=256) -> fp32
    {
        dim3 grid(2, NP / 128);
        mma_gemm_kernel<0><<<grid, 256, MMA_SMEM>>>(
            (const __nv_bfloat16*)p_hh, (const __nv_bfloat16*)p_hl,
            (const __nv_bfloat16*)p_w2h, (const __nv_bfloat16*)p_w2l,
            (float*)p_X, nullptr, nullptr, nullptr, 256, 256);
    }

    // K3: fused gather + f_delta + X-transform -> fa hi/lo
    fused_xform_kernel<<<NP / FW, FW * 32>>>(coords, feats, knn, Wd, bd);

    // K4: out = f_all @ Wconv + bconv   (M=NP, N=128, K=1536) -> fp32
    {
        dim3 grid(1, NP / 128);
        mma_gemm_kernel<0><<<grid, 256, MMA_SMEM>>>(
            (const __nv_bfloat16*)p_fh, (const __nv_bfloat16*)p_fl,
            (const __nv_bfloat16*)p_wch, (const __nv_bfloat16*)p_wcl,
            out, nullptr, nullptr, bconv, 1536, 128);
    }
}